// round 2
// baseline (speedup 1.0000x reference)
#include <cuda_runtime.h>
#include <math.h>
#include <stdint.h>

#define BN   2
#define TT   256
#define HID  2048
#define NH   16
#define HD   128
#define BH   32          // BN*NH
#define CS   8           // timesteps per chunk
#define NC   32          // TT/CS
#define NCG  30
#define MROWS (BN*TT)    // 512

// ------------------------- scratch (device globals) -------------------------
__device__ float g_Q[BH*TT*HD];        // [bh][t][d], l2-normalized q
__device__ float g_K[BH*TT*HD];        // [bh][t][d], l2-normalized k
__device__ float g_V[BH*TT*HD];        // [bh][t][d]
__device__ float g_O[MROWS*NH*HD];     // [(b*T+t)*NH+h][d]  raw mesa output
__device__ float g_Of[MROWS*HID];      // rms-normed, [512][2048]
__device__ float g_g[BH*TT];           // log-sigmoid gate
__device__ float g_G[BH*TT];           // inclusive cumsum of g over t
__device__ float g_beta[BH*TT];
__device__ float g_Skk[BH*NC*HD*HD];   // chunk sums -> checkpoints (in place)
__device__ float g_Skv[BH*NC*HD*HD];

// ------------------------- helpers -------------------------
__device__ __forceinline__ float warp_sum(float v){
#pragma unroll
  for (int o = 16; o; o >>= 1) v += __shfl_xor_sync(0xffffffffu, v, o);
  return v;
}

// ------------------------- K1: gates (beta, g) -------------------------
// grid 512 (= b*T+t), 256 threads
__global__ void __launch_bounds__(256) k_gates(const float* __restrict__ x,
                                               const float* __restrict__ Wa,
                                               const float* __restrict__ ba,
                                               const float* __restrict__ Wb,
                                               const float* __restrict__ bb){
  int row = blockIdx.x;           // b*256 + t
  int b = row >> 8, t = row & 255;
  __shared__ float xr[HID];
  __shared__ float red[8][32];
  int tid = threadIdx.x;
  const float4* xp = (const float4*)(x + (size_t)row * HID);
#pragma unroll
  for (int idx = tid; idx < HID/4; idx += 256){
    float4 v = xp[idx];
    *(float4*)&xr[idx*4] = v;
  }
  __syncthreads();
  int o = tid & 31, k8 = tid >> 5;     // o: which output (0..15 Wa, 16..31 Wb)
  float partial = 0.f;
  if (o < 16){
    for (int c = k8*256; c < k8*256+256; c++) partial += xr[c] * Wa[c*NH + o];
  } else {
    int oo = o - 16;
    for (int c = k8*256; c < k8*256+256; c++) partial += xr[c] * Wb[c*NH + oo];
  }
  red[k8][o] = partial;
  __syncthreads();
  if (tid < 32){
    float v = 0.f;
#pragma unroll
    for (int u = 0; u < 8; u++) v += red[u][tid];
    if (tid < 16){
      float z = v + ba[tid];
      float ls = (z >= 0.f) ? -log1pf(expf(-z)) : (z - log1pf(expf(z)));
      g_g[(b*NH + tid)*TT + t] = ls;
    } else {
      int hh = tid - 16;
      float z = v + bb[hh];
      g_beta[(b*NH + hh)*TT + t] = 1.f / (1.f + expf(-z));
    }
  }
}

// ------------------------- K2: cumsum of g over t -------------------------
// grid 32 (bh), 256 threads
__global__ void __launch_bounds__(256) k_scanG(){
  int bh = blockIdx.x;
  int t = threadIdx.x;
  __shared__ float s[TT];
  s[t] = g_g[bh*TT + t];
  __syncthreads();
  for (int off = 1; off < TT; off <<= 1){
    float u = (t >= off) ? s[t - off] : 0.f;
    __syncthreads();
    s[t] += u;
    __syncthreads();
  }
  g_G[bh*TT + t] = s[t];
}

// ------------------------- K3: QKV projections + SiLU -------------------------
// C[512,2048] = silu(X @ W); tile 128x64, Kblk 16; grid (32,4,3), 256 threads
__global__ void __launch_bounds__(256) k_qkv(const float* __restrict__ X,
                                             const float* __restrict__ Wq,
                                             const float* __restrict__ Wk,
                                             const float* __restrict__ Wv){
  const float* W = blockIdx.z == 0 ? Wq : (blockIdx.z == 1 ? Wk : Wv);
  float* DST     = blockIdx.z == 0 ? g_Q : (blockIdx.z == 1 ? g_K : g_V);
  __shared__ __align__(16) float As[16][132];
  __shared__ __align__(16) float Bs[16][68];
  int tid = threadIdx.x;
  int ty = tid >> 4, tx = tid & 15;
  int m0 = blockIdx.y * 128, n0 = blockIdx.x * 64;
  float acc[8][4];
#pragma unroll
  for (int ii = 0; ii < 8; ii++)
#pragma unroll
    for (int jj = 0; jj < 4; jj++) acc[ii][jj] = 0.f;

  for (int kb = 0; kb < HID; kb += 16){
#pragma unroll
    for (int it = 0; it < 2; it++){
      int f = tid*2 + it; int m = f >> 2, c4 = f & 3;
      float4 v = *(const float4*)&X[(size_t)(m0 + m)*HID + kb + c4*4];
      As[c4*4+0][m] = v.x; As[c4*4+1][m] = v.y;
      As[c4*4+2][m] = v.z; As[c4*4+3][m] = v.w;
    }
    {
      int kk = tid >> 4, n4 = tid & 15;
      float4 v = *(const float4*)&W[(size_t)(kb + kk)*HID + n0 + n4*4];
      *(float4*)&Bs[kk][n4*4] = v;
    }
    __syncthreads();
#pragma unroll
    for (int k = 0; k < 16; k++){
      float4 a0 = *(float4*)&As[k][ty*8];
      float4 a1 = *(float4*)&As[k][ty*8+4];
      float4 bq = *(float4*)&Bs[k][tx*4];
      float a[8] = {a0.x,a0.y,a0.z,a0.w,a1.x,a1.y,a1.z,a1.w};
      float bb4[4] = {bq.x,bq.y,bq.z,bq.w};
#pragma unroll
      for (int ii = 0; ii < 8; ii++)
#pragma unroll
        for (int jj = 0; jj < 4; jj++) acc[ii][jj] += a[ii]*bb4[jj];
    }
    __syncthreads();
  }
  // epilogue: silu + scatter to [bh][t][d]
  int n = n0 + tx*4;
  int h = n >> 7, dd = n & 127;
#pragma unroll
  for (int ii = 0; ii < 8; ii++){
    int m = m0 + ty*8 + ii;
    int b = m >> 8, t = m & 255;
    float4 ov;
    float z0 = acc[ii][0], z1 = acc[ii][1], z2 = acc[ii][2], z3 = acc[ii][3];
    ov.x = z0 / (1.f + expf(-z0));
    ov.y = z1 / (1.f + expf(-z1));
    ov.z = z2 / (1.f + expf(-z2));
    ov.w = z3 / (1.f + expf(-z3));
    *(float4*)&DST[(size_t)((b*NH + h)*TT + t)*HD + dd] = ov;
  }
}

// ------------------------- K4: l2 normalize q, k rows -------------------------
// grid (8192, 2), 128 threads
__global__ void __launch_bounds__(128) k_l2(){
  int row = blockIdx.x;
  float* A = blockIdx.y == 0 ? g_Q : g_K;
  int i = threadIdx.x;
  float v = A[(size_t)row*HD + i];
  float ss = warp_sum(v*v);
  __shared__ float w4[4];
  if ((i & 31) == 0) w4[i >> 5] = ss;
  __syncthreads();
  float n = sqrtf(w4[0] + w4[1] + w4[2] + w4[3]);
  A[(size_t)row*HD + i] = v / fmaxf(n, 1e-12f);
}

// ------------------------- K5: per-chunk weighted outer-product sums ------------
// S_c = sum_{s in chunk} beta_s * exp(G_end - G_s) * k_s k_s^T (and k v^T)
// grid (NC, BH), 256 threads
__global__ void __launch_bounds__(256) k_chunksum(){
  int c = blockIdx.x, bh = blockIdx.y;
  __shared__ float ks[CS*HD], vs[CS*HD], coef[CS];
  int tid = threadIdx.x;
  const float* Kb = g_K + (size_t)(bh*TT + c*CS)*HD;
  const float* Vb = g_V + (size_t)(bh*TT + c*CS)*HD;
  for (int idx = tid; idx < CS*HD; idx += 256){ ks[idx] = Kb[idx]; vs[idx] = Vb[idx]; }
  if (tid < CS){
    float Gend = g_G[bh*TT + c*CS + CS - 1];
    float Gs   = g_G[bh*TT + c*CS + tid];
    coef[tid] = g_beta[bh*TT + c*CS + tid] * expf(Gend - Gs);
  }
  __syncthreads();
  int i0 = (tid >> 4) * 8, j0 = (tid & 15) * 8;
  size_t base = ((size_t)(bh*NC + c) << 14);
  float acc[8][8];
  // pass 1: kk
#pragma unroll
  for (int ii = 0; ii < 8; ii++)
#pragma unroll
    for (int jj = 0; jj < 8; jj++) acc[ii][jj] = 0.f;
#pragma unroll
  for (int s = 0; s < CS; s++){
    float cj[8];
#pragma unroll
    for (int jj = 0; jj < 8; jj++) cj[jj] = ks[s*HD + j0 + jj] * coef[s];
#pragma unroll
    for (int ii = 0; ii < 8; ii++){
      float kv = ks[s*HD + i0 + ii];
#pragma unroll
      for (int jj = 0; jj < 8; jj++) acc[ii][jj] += kv * cj[jj];
    }
  }
#pragma unroll
  for (int ii = 0; ii < 8; ii++){
    *(float4*)&g_Skk[base + (size_t)(i0+ii)*HD + j0]     = *(float4*)&acc[ii][0];
    *(float4*)&g_Skk[base + (size_t)(i0+ii)*HD + j0 + 4] = *(float4*)&acc[ii][4];
  }
  // pass 2: kv
#pragma unroll
  for (int ii = 0; ii < 8; ii++)
#pragma unroll
    for (int jj = 0; jj < 8; jj++) acc[ii][jj] = 0.f;
#pragma unroll
  for (int s = 0; s < CS; s++){
    float cj[8];
#pragma unroll
    for (int jj = 0; jj < 8; jj++) cj[jj] = vs[s*HD + j0 + jj] * coef[s];
#pragma unroll
    for (int ii = 0; ii < 8; ii++){
      float kv = ks[s*HD + i0 + ii];
#pragma unroll
      for (int jj = 0; jj < 8; jj++) acc[ii][jj] += kv * cj[jj];
    }
  }
#pragma unroll
  for (int ii = 0; ii < 8; ii++){
    *(float4*)&g_Skv[base + (size_t)(i0+ii)*HD + j0]     = *(float4*)&acc[ii][0];
    *(float4*)&g_Skv[base + (size_t)(i0+ii)*HD + j0 + 4] = *(float4*)&acc[ii][4];
  }
}

// ------------------------- K6: scan over chunks (in place) -------------------------
// After this, g_Skk[bh][c] = H_kk at END of chunk c (same for kv).
// grid (BH, 64), 256 threads
__global__ void __launch_bounds__(256) k_scan(){
  int bh = blockIdx.x;
  int e = blockIdx.y * 256 + threadIdx.x;   // element in 128x128
  __shared__ float dc[NC];
  if (threadIdx.x < NC){
    int c = threadIdx.x;
    dc[c] = (c == 0) ? 0.f
          : expf(g_G[bh*TT + c*CS + CS - 1] - g_G[bh*TT + (c-1)*CS + CS - 1]);
  }
  __syncthreads();
  float a = 0.f, bacc = 0.f;
#pragma unroll 4
  for (int c = 0; c < NC; c++){
    size_t off = ((size_t)(bh*NC + c) << 14) + e;
    a    = a    * dc[c] + g_Skk[off]; g_Skk[off] = a;
    bacc = bacc * dc[c] + g_Skv[off]; g_Skv[off] = bacc;
  }
}

// ------------------------- K7: per-chunk sequential solve -------------------------
// grid (NC, BH), 512 threads. Thread (i = tid&127, qq = tid>>7) owns
// H[i][qq*32 .. qq*32+31] in registers for both H_kk and H_kv.
#define MV_PART(Hreg) do { \
  const float* u_ = &uv[qq*32]; \
  float s0=0.f, s1=0.f, s2=0.f, s3=0.f; \
  _Pragma("unroll") \
  for (int jj = 0; jj < 32; jj += 4){ \
    s0 += Hreg[jj+0]*u_[jj+0]; \
    s1 += Hreg[jj+1]*u_[jj+1]; \
    s2 += Hreg[jj+2]*u_[jj+2]; \
    s3 += Hreg[jj+3]*u_[jj+3]; \
  } \
  part[qq*128 + i] = (s0+s1)+(s2+s3); \
} while(0)

__global__ void __launch_bounds__(512,1) k_solve(const float* __restrict__ lp){
  int c = blockIdx.x, bh = blockIdx.y;
  int b = bh >> 4, h = bh & 15;
  int tid = threadIdx.x;
  int qq = tid >> 7;
  int i  = tid & 127;
  __shared__ float ksm[HD], vsm[HD], qsm[HD], lam[HD], dg[HD], uv[HD];
  __shared__ float part[4*HD];
  __shared__ float wsum[4], wsum2[4];

  if (tid < HD){
    float z = lp[h*HD + i];
    float sp = (z > 20.f) ? z : log1pf(expf(z));
    lam[i] = sp + 0.25f;
  }
  // load start state (checkpoint of previous chunk)
  float hkk[32], hkv[32];
  if (c == 0){
#pragma unroll
    for (int jj = 0; jj < 32; jj++){ hkk[jj] = 0.f; hkv[jj] = 0.f; }
  } else {
    size_t base = ((size_t)(bh*NC + (c-1)) << 14) + (size_t)i*HD + qq*32;
#pragma unroll
    for (int jj = 0; jj < 32; jj += 4){
      float4 a = *(const float4*)&g_Skk[base + jj];
      hkk[jj] = a.x; hkk[jj+1] = a.y; hkk[jj+2] = a.z; hkk[jj+3] = a.w;
      float4 v = *(const float4*)&g_Skv[base + jj];
      hkv[jj] = v.x; hkv[jj+1] = v.y; hkv[jj+2] = v.z; hkv[jj+3] = v.w;
    }
  }
  __syncthreads();

  for (int t = 0; t < CS; t++){
    int ts = c*CS + t;
    if (tid < HD){
      size_t r = (size_t)(bh*TT + ts)*HD + i;
      ksm[i] = g_K[r]; vsm[i] = g_V[r]; qsm[i] = g_Q[r];
    }
    __syncthreads();
    float dec = expf(g_g[bh*TT + ts]);
    float w   = g_beta[bh*TT + ts];
    float ki  = ksm[i] * w;
    {
      const float* kk = &ksm[qq*32];
      const float* vv = &vsm[qq*32];
#pragma unroll
      for (int jj = 0; jj < 32; jj++){
        hkk[jj] = hkk[jj]*dec + ki*kk[jj];
        hkv[jj] = hkv[jj]*dec + ki*vv[jj];
      }
    }
    if (qq == (i >> 5)) dg[i] = hkk[i & 31];
    __syncthreads();

    // ---- CG init ----
    float x = 0.f, r = 0.f, p = 0.f, d = 0.f;
    bool done = false;
    if (tid < HD){
      x = qsm[i] / (dg[i] + lam[i] + 1e-8f);
      uv[i] = x;
    }
    __syncthreads();
    MV_PART(hkk);
    __syncthreads();
    if (tid < HD){
      float Ax = part[i] + part[128+i] + part[256+i] + part[384+i] + lam[i]*x;
      r = qsm[i] - Ax;
      p = r;
      uv[i] = p;
      float rr = warp_sum(r*r);
      if ((tid & 31) == 0) wsum[tid >> 5] = rr;
    }
    __syncthreads();
    if (tid < HD) d = wsum[0] + wsum[1] + wsum[2] + wsum[3];

    // ---- CG iterations ----
    for (int it = 0; it < NCG; it++){
      MV_PART(hkk);
      __syncthreads();
      float qi = 0.f;
      if (tid < HD){
        qi = part[i] + part[128+i] + part[256+i] + part[384+i] + lam[i]*p;
        float t1 = warp_sum(p*qi);
        if ((tid & 31) == 0) wsum[tid >> 5] = t1;
      }
      __syncthreads();
      if (tid < HD){
        float pq = wsum[0] + wsum[1] + wsum[2] + wsum[3];
        done = done || (d < 1e-10f);
        done = done || (fabsf(pq) < 1e-10f);
        float alpha = done ? 0.f : d / pq;
        x += alpha * p;
        r -= alpha * qi;
        float rr = warp_sum(r*r);
        if ((tid & 31) == 0) wsum2[tid >> 5] = rr;
      }
      __syncthreads();
      if (tid < HD){
        float dn = wsum2[0] + wsum2[1] + wsum2[2] + wsum2[3];
        float bet = done ? 0.f : dn / d;
        if (!done){ p = r + bet * p; d = dn; }
        uv[i] = p;
      }
      __syncthreads();
    }

    // ---- output o = H_kv @ x ----
    if (tid < HD) uv[i] = x;
    __syncthreads();
    MV_PART(hkv);
    __syncthreads();
    if (tid < HD){
      float o = part[i] + part[128+i] + part[256+i] + part[384+i];
      g_O[((size_t)(b*TT + ts)*NH + h)*HD + i] = o;
    }
    __syncthreads();
  }
}

// ------------------------- K8: rms norm -------------------------
// grid 8192 (= (b*T+t)*NH+h), 128 threads
__global__ void __launch_bounds__(128) k_rms(const float* __restrict__ w){
  int row = blockIdx.x;
  int i = threadIdx.x;
  float v = g_O[(size_t)row*HD + i];
  float ss = warp_sum(v*v);
  __shared__ float w4[4];
  if ((i & 31) == 0) w4[i >> 5] = ss;
  __syncthreads();
  float ms = (w4[0] + w4[1] + w4[2] + w4[3]) * (1.f/128.f);
  float rms = sqrtf(ms + 1e-6f);
  g_Of[(size_t)row*HD + i] = v / rms * w[i];
}

// ------------------------- K9: output projection -------------------------
// out[512,2048] = g_Of @ Wo; grid (32,4), 256 threads
__global__ void __launch_bounds__(256) k_out(const float* __restrict__ Wo,
                                             float* __restrict__ out){
  __shared__ __align__(16) float As[16][132];
  __shared__ __align__(16) float Bs[16][68];
  int tid = threadIdx.x;
  int ty = tid >> 4, tx = tid & 15;
  int m0 = blockIdx.y * 128, n0 = blockIdx.x * 64;
  float acc[8][4];
#pragma unroll
  for (int ii = 0; ii < 8; ii++)
#pragma unroll
    for (int jj = 0; jj < 4; jj++) acc[ii][jj] = 0.f;

  for (int kb = 0; kb < HID; kb += 16){
#pragma unroll
    for (int it = 0; it < 2; it++){
      int f = tid*2 + it; int m = f >> 2, c4 = f & 3;
      float4 v = *(const float4*)&g_Of[(size_t)(m0 + m)*HID + kb + c4*4];
      As[c4*4+0][m] = v.x; As[c4*4+1][m] = v.y;
      As[c4*4+2][m] = v.z; As[c4*4+3][m] = v.w;
    }
    {
      int kk = tid >> 4, n4 = tid & 15;
      float4 v = *(const float4*)&Wo[(size_t)(kb + kk)*HID + n0 + n4*4];
      *(float4*)&Bs[kk][n4*4] = v;
    }
    __syncthreads();
#pragma unroll
    for (int k = 0; k < 16; k++){
      float4 a0 = *(float4*)&As[k][ty*8];
      float4 a1 = *(float4*)&As[k][ty*8+4];
      float4 bq = *(float4*)&Bs[k][tx*4];
      float a[8] = {a0.x,a0.y,a0.z,a0.w,a1.x,a1.y,a1.z,a1.w};
      float bb4[4] = {bq.x,bq.y,bq.z,bq.w};
#pragma unroll
      for (int ii = 0; ii < 8; ii++)
#pragma unroll
        for (int jj = 0; jj < 4; jj++) acc[ii][jj] += a[ii]*bb4[jj];
    }
    __syncthreads();
  }
#pragma unroll
  for (int ii = 0; ii < 8; ii++){
    int m = m0 + ty*8 + ii;
    *(float4*)&out[(size_t)m*HID + n0 + tx*4] = *(float4*)&acc[ii][0];
  }
}

// ------------------------- launcher -------------------------
extern "C" void kernel_launch(void* const* d_in, const int* in_sizes, int n_in,
                              void* d_out, int out_size){
  const float* x    = (const float*)d_in[0];
  const float* Wq   = (const float*)d_in[1];
  const float* Wk   = (const float*)d_in[2];
  const float* Wv   = (const float*)d_in[3];
  const float* Wa   = (const float*)d_in[4];
  const float* ba   = (const float*)d_in[5];
  const float* Wb   = (const float*)d_in[6];
  const float* bb   = (const float*)d_in[7];
  const float* lpar = (const float*)d_in[8];
  const float* onw  = (const float*)d_in[9];
  const float* Wo   = (const float*)d_in[10];
  float* out = (float*)d_out;

  k_gates<<<MROWS, 256>>>(x, Wa, ba, Wb, bb);
  k_scanG<<<BH, 256>>>();
  k_qkv<<<dim3(32, 4, 3), 256>>>(x, Wq, Wk, Wv);
  k_l2<<<dim3(BH*TT, 2), 128>>>();
  k_chunksum<<<dim3(NC, BH), 256>>>();
  k_scan<<<dim3(BH, 64), 256>>>();
  k_solve<<<dim3(NC, BH), 512>>>(lpar);
  k_rms<<<MROWS*NH, 128>>>(onw);
  k_out<<<dim3(32, 4), 256>>>(Wo, out);
}

// round 3
// speedup vs baseline: 1.2990x; 1.2990x over previous
#include <cuda_runtime.h>
#include <math.h>
#include <stdint.h>

#define BN   2
#define TT   256
#define HID  2048
#define NH   16
#define HD   128
#define BH   32          // BN*NH
#define CS   8           // timesteps per chunk (= batched CG RHS count)
#define NC   32          // TT/CS
#define NCG  30
#define MROWS (BN*TT)    // 512

typedef unsigned long long ull;

// ------------------------- scratch (device globals) -------------------------
__device__ float g_Q[BH*TT*HD];
__device__ float g_K[BH*TT*HD];
__device__ float g_V[BH*TT*HD];
__device__ float g_O[MROWS*NH*HD];
__device__ float g_Of[MROWS*HID];
__device__ float g_g[BH*TT];
__device__ float g_G[BH*TT];
__device__ float g_beta[BH*TT];
__device__ float g_Skk[BH*NC*HD*HD];
__device__ float g_Skv[BH*NC*HD*HD];

// ------------------------- helpers -------------------------
__device__ __forceinline__ float warp_sum(float v){
#pragma unroll
  for (int o = 16; o; o >>= 1) v += __shfl_xor_sync(0xffffffffu, v, o);
  return v;
}
__device__ __forceinline__ ull bcast2(float x){
  ull r; asm("mov.b64 %0, {%1, %1};" : "=l"(r) : "f"(x)); return r;
}
__device__ __forceinline__ void ffma2(ull& d, ull a, ull b){
  asm("fma.rn.f32x2 %0, %1, %2, %0;" : "+l"(d) : "l"(a), "l"(b));
}
__device__ __forceinline__ float2 unpack2(ull v){
  float2 f; asm("mov.b64 {%0, %1}, %2;" : "=f"(f.x), "=f"(f.y) : "l"(v)); return f;
}

// ------------------------- K1: gates (beta, g) -------------------------
__global__ void __launch_bounds__(256) k_gates(const float* __restrict__ x,
                                               const float* __restrict__ Wa,
                                               const float* __restrict__ ba,
                                               const float* __restrict__ Wb,
                                               const float* __restrict__ bb){
  int row = blockIdx.x;
  int b = row >> 8, t = row & 255;
  __shared__ float xr[HID];
  __shared__ float red[8][32];
  int tid = threadIdx.x;
  const float4* xp = (const float4*)(x + (size_t)row * HID);
#pragma unroll
  for (int idx = tid; idx < HID/4; idx += 256){
    float4 v = xp[idx];
    *(float4*)&xr[idx*4] = v;
  }
  __syncthreads();
  int o = tid & 31, k8 = tid >> 5;
  float partial = 0.f;
  if (o < 16){
    for (int c = k8*256; c < k8*256+256; c++) partial += xr[c] * Wa[c*NH + o];
  } else {
    int oo = o - 16;
    for (int c = k8*256; c < k8*256+256; c++) partial += xr[c] * Wb[c*NH + oo];
  }
  red[k8][o] = partial;
  __syncthreads();
  if (tid < 32){
    float v = 0.f;
#pragma unroll
    for (int u = 0; u < 8; u++) v += red[u][tid];
    if (tid < 16){
      float z = v + ba[tid];
      float ls = (z >= 0.f) ? -log1pf(expf(-z)) : (z - log1pf(expf(z)));
      g_g[(b*NH + tid)*TT + t] = ls;
    } else {
      int hh = tid - 16;
      float z = v + bb[hh];
      g_beta[(b*NH + hh)*TT + t] = 1.f / (1.f + expf(-z));
    }
  }
}

// ------------------------- K2: cumsum of g over t -------------------------
__global__ void __launch_bounds__(256) k_scanG(){
  int bh = blockIdx.x;
  int t = threadIdx.x;
  __shared__ float s[TT];
  s[t] = g_g[bh*TT + t];
  __syncthreads();
  for (int off = 1; off < TT; off <<= 1){
    float u = (t >= off) ? s[t - off] : 0.f;
    __syncthreads();
    s[t] += u;
    __syncthreads();
  }
  g_G[bh*TT + t] = s[t];
}

// ------------------------- K3: QKV projections + SiLU (f32x2) ----------------
__global__ void __launch_bounds__(256) k_qkv(const float* __restrict__ X,
                                             const float* __restrict__ Wq,
                                             const float* __restrict__ Wk,
                                             const float* __restrict__ Wv){
  const float* W = blockIdx.z == 0 ? Wq : (blockIdx.z == 1 ? Wk : Wv);
  float* DST     = blockIdx.z == 0 ? g_Q : (blockIdx.z == 1 ? g_K : g_V);
  __shared__ __align__(16) float As[16][132];
  __shared__ __align__(16) float Bs[16][68];
  int tid = threadIdx.x;
  int ty = tid >> 4, tx = tid & 15;
  int m0 = blockIdx.y * 128, n0 = blockIdx.x * 64;
  ull acc2[4][4];
#pragma unroll
  for (int ii = 0; ii < 4; ii++)
#pragma unroll
    for (int jj = 0; jj < 4; jj++) acc2[ii][jj] = 0ull;

  for (int kb = 0; kb < HID; kb += 16){
#pragma unroll
    for (int it = 0; it < 2; it++){
      int f = tid*2 + it; int m = f >> 2, c4 = f & 3;
      float4 v = *(const float4*)&X[(size_t)(m0 + m)*HID + kb + c4*4];
      As[c4*4+0][m] = v.x; As[c4*4+1][m] = v.y;
      As[c4*4+2][m] = v.z; As[c4*4+3][m] = v.w;
    }
    {
      int kk = tid >> 4, n4 = tid & 15;
      float4 v = *(const float4*)&W[(size_t)(kb + kk)*HID + n0 + n4*4];
      *(float4*)&Bs[kk][n4*4] = v;
    }
    __syncthreads();
#pragma unroll
    for (int k = 0; k < 16; k++){
      const ulonglong2* ap = (const ulonglong2*)&As[k][ty*8];
      ulonglong2 aA = ap[0], aB = ap[1];
      float4 bq = *(const float4*)&Bs[k][tx*4];
      ull b0 = bcast2(bq.x), b1 = bcast2(bq.y), b2 = bcast2(bq.z), b3 = bcast2(bq.w);
      ffma2(acc2[0][0], aA.x, b0); ffma2(acc2[0][1], aA.x, b1);
      ffma2(acc2[0][2], aA.x, b2); ffma2(acc2[0][3], aA.x, b3);
      ffma2(acc2[1][0], aA.y, b0); ffma2(acc2[1][1], aA.y, b1);
      ffma2(acc2[1][2], aA.y, b2); ffma2(acc2[1][3], aA.y, b3);
      ffma2(acc2[2][0], aB.x, b0); ffma2(acc2[2][1], aB.x, b1);
      ffma2(acc2[2][2], aB.x, b2); ffma2(acc2[2][3], aB.x, b3);
      ffma2(acc2[3][0], aB.y, b0); ffma2(acc2[3][1], aB.y, b1);
      ffma2(acc2[3][2], aB.y, b2); ffma2(acc2[3][3], aB.y, b3);
    }
    __syncthreads();
  }
  int n = n0 + tx*4;
  int h = n >> 7, dd = n & 127;
#pragma unroll
  for (int m2 = 0; m2 < 4; m2++){
    float2 c0 = unpack2(acc2[m2][0]);
    float2 c1 = unpack2(acc2[m2][1]);
    float2 c2 = unpack2(acc2[m2][2]);
    float2 c3 = unpack2(acc2[m2][3]);
#pragma unroll
    for (int half = 0; half < 2; half++){
      int m = m0 + ty*8 + m2*2 + half;
      int b = m >> 8, t = m & 255;
      float z0 = half ? c0.y : c0.x;
      float z1 = half ? c1.y : c1.x;
      float z2 = half ? c2.y : c2.x;
      float z3 = half ? c3.y : c3.x;
      float4 ov;
      ov.x = z0 / (1.f + expf(-z0));
      ov.y = z1 / (1.f + expf(-z1));
      ov.z = z2 / (1.f + expf(-z2));
      ov.w = z3 / (1.f + expf(-z3));
      *(float4*)&DST[(size_t)((b*NH + h)*TT + t)*HD + dd] = ov;
    }
  }
}

// ------------------------- K4: l2 normalize q, k rows -------------------------
__global__ void __launch_bounds__(128) k_l2(){
  int row = blockIdx.x;
  float* A = blockIdx.y == 0 ? g_Q : g_K;
  int i = threadIdx.x;
  float v = A[(size_t)row*HD + i];
  float ss = warp_sum(v*v);
  __shared__ float w4[4];
  if ((i & 31) == 0) w4[i >> 5] = ss;
  __syncthreads();
  float n = sqrtf(w4[0] + w4[1] + w4[2] + w4[3]);
  A[(size_t)row*HD + i] = v / fmaxf(n, 1e-12f);
}

// ------------------------- K5: per-chunk weighted outer-product sums ----------
__global__ void __launch_bounds__(256) k_chunksum(){
  int c = blockIdx.x, bh = blockIdx.y;
  __shared__ float ks[CS*HD], vs[CS*HD], coef[CS];
  int tid = threadIdx.x;
  const float* Kb = g_K + (size_t)(bh*TT + c*CS)*HD;
  const float* Vb = g_V + (size_t)(bh*TT + c*CS)*HD;
  for (int idx = tid; idx < CS*HD; idx += 256){ ks[idx] = Kb[idx]; vs[idx] = Vb[idx]; }
  if (tid < CS){
    float Gend = g_G[bh*TT + c*CS + CS - 1];
    float Gs   = g_G[bh*TT + c*CS + tid];
    coef[tid] = g_beta[bh*TT + c*CS + tid] * expf(Gend - Gs);
  }
  __syncthreads();
  int i0 = (tid >> 4) * 8, j0 = (tid & 15) * 8;
  size_t base = ((size_t)(bh*NC + c) << 14);
  float acc[8][8];
#pragma unroll
  for (int ii = 0; ii < 8; ii++)
#pragma unroll
    for (int jj = 0; jj < 8; jj++) acc[ii][jj] = 0.f;
#pragma unroll
  for (int s = 0; s < CS; s++){
    float cj[8];
#pragma unroll
    for (int jj = 0; jj < 8; jj++) cj[jj] = ks[s*HD + j0 + jj] * coef[s];
#pragma unroll
    for (int ii = 0; ii < 8; ii++){
      float kv = ks[s*HD + i0 + ii];
#pragma unroll
      for (int jj = 0; jj < 8; jj++) acc[ii][jj] += kv * cj[jj];
    }
  }
#pragma unroll
  for (int ii = 0; ii < 8; ii++){
    *(float4*)&g_Skk[base + (size_t)(i0+ii)*HD + j0]     = *(float4*)&acc[ii][0];
    *(float4*)&g_Skk[base + (size_t)(i0+ii)*HD + j0 + 4] = *(float4*)&acc[ii][4];
  }
#pragma unroll
  for (int ii = 0; ii < 8; ii++)
#pragma unroll
    for (int jj = 0; jj < 8; jj++) acc[ii][jj] = 0.f;
#pragma unroll
  for (int s = 0; s < CS; s++){
    float cj[8];
#pragma unroll
    for (int jj = 0; jj < 8; jj++) cj[jj] = vs[s*HD + j0 + jj] * coef[s];
#pragma unroll
    for (int ii = 0; ii < 8; ii++){
      float kv = ks[s*HD + i0 + ii];
#pragma unroll
      for (int jj = 0; jj < 8; jj++) acc[ii][jj] += kv * cj[jj];
    }
  }
#pragma unroll
  for (int ii = 0; ii < 8; ii++){
    *(float4*)&g_Skv[base + (size_t)(i0+ii)*HD + j0]     = *(float4*)&acc[ii][0];
    *(float4*)&g_Skv[base + (size_t)(i0+ii)*HD + j0 + 4] = *(float4*)&acc[ii][4];
  }
}

// ------------------------- K6: scan over chunks (in place) --------------------
__global__ void __launch_bounds__(256) k_scan(){
  int bh = blockIdx.x;
  int e = blockIdx.y * 256 + threadIdx.x;
  __shared__ float dc[NC];
  if (threadIdx.x < NC){
    int c = threadIdx.x;
    dc[c] = (c == 0) ? 0.f
          : expf(g_G[bh*TT + c*CS + CS - 1] - g_G[bh*TT + (c-1)*CS + CS - 1]);
  }
  __syncthreads();
  float a = 0.f, bacc = 0.f;
#pragma unroll 4
  for (int c = 0; c < NC; c++){
    size_t off = ((size_t)(bh*NC + c) << 14) + e;
    a    = a    * dc[c] + g_Skk[off]; g_Skk[off] = a;
    bacc = bacc * dc[c] + g_Skv[off]; g_Skv[off] = bacc;
  }
}

// ------------------------- K7: batched 8-RHS CG solve -------------------------
// grid (NC, BH), 512 threads. Thread (i = tid&127, qq = tid>>7) owns
// H0[i][qq*32 .. +31] in regs. All 8 timestep solves of the chunk run in
// lockstep; A_t u = c_t*(H0 u) + sum_s Wc[t][s]*(k_s . u)*k_s + lam*u.

// base matvec (all 512 threads) + 8x8 dot matrix (warp per 4 pairs)
#define PHASE_A(HREG, MSM) do { \
  ull y0=0ull, y1=0ull, y2=0ull, y3=0ull; \
  _Pragma("unroll") \
  for (int jj = 0; jj < 32; jj++){ \
    const ulonglong2* pr = (const ulonglong2*)&P[qq*32+jj][0]; \
    ulonglong2 pa = pr[0], pb = pr[1]; \
    ull hb = bcast2(HREG[jj]); \
    ffma2(y0, hb, pa.x); ffma2(y1, hb, pa.y); \
    ffma2(y2, hb, pb.x); ffma2(y3, hb, pb.y); \
  } \
  ((ulonglong2*)&part[qq][i][0])[0] = make_ulonglong2(y0, y1); \
  ((ulonglong2*)&part[qq][i][0])[1] = make_ulonglong2(y2, y3); \
  { int w_ = tid >> 5, lane_ = tid & 31; \
    _Pragma("unroll") \
    for (int pp = 0; pp < 4; pp++){ \
      int idx_ = (w_ << 2) | pp; int s_ = idx_ >> 3, t_ = idx_ & 7; \
      float4 kv_ = *(const float4*)&MSM[s_][lane_*4]; \
      float4 pv_ = *(const float4*)&PT[t_][lane_*4]; \
      float pd_ = kv_.x*pv_.x + kv_.y*pv_.y + kv_.z*pv_.z + kv_.w*pv_.w; \
      pd_ = warp_sum(pd_); \
      if (lane_ == 0) dots[s_][t_] = pd_; \
    } } \
} while(0)

// OUTV[t] = cdec[t]*sum_qq(part) + sum_s Wc[t][s]*dots[s][t]*Ksm[s][i]
#define ASSEMBLE(OUTV) do { \
  float yv_[CS]; \
  _Pragma("unroll") \
  for (int q2 = 0; q2 < 4; q2++){ \
    float4 u0_ = *(const float4*)&part[q2][i][0]; \
    float4 u1_ = *(const float4*)&part[q2][i][4]; \
    if (q2 == 0){ yv_[0]=u0_.x; yv_[1]=u0_.y; yv_[2]=u0_.z; yv_[3]=u0_.w; \
                  yv_[4]=u1_.x; yv_[5]=u1_.y; yv_[6]=u1_.z; yv_[7]=u1_.w; } \
    else { yv_[0]+=u0_.x; yv_[1]+=u0_.y; yv_[2]+=u0_.z; yv_[3]+=u0_.w; \
           yv_[4]+=u1_.x; yv_[5]+=u1_.y; yv_[6]+=u1_.z; yv_[7]+=u1_.w; } \
  } \
  float ksv_[CS]; \
  _Pragma("unroll") \
  for (int s_ = 0; s_ < CS; s_++) ksv_[s_] = Ksm[s_][i]; \
  _Pragma("unroll") \
  for (int t_ = 0; t_ < CS; t_++){ \
    float a_ = cdec[t_] * yv_[t_]; \
    _Pragma("unroll") \
    for (int s_ = 0; s_ < CS; s_++) a_ += (Wc[t_][s_] * dots[s_][t_]) * ksv_[s_]; \
    OUTV[t_] = a_; \
  } \
} while(0)

__global__ void __launch_bounds__(512,1) k_solve(const float* __restrict__ lp){
  int c = blockIdx.x, bh = blockIdx.y;
  int b = bh >> 4, h = bh & 15;
  int tid = threadIdx.x;
  int qq = tid >> 7;
  int i  = tid & 127;
  int g0 = bh*TT + c*CS;

  __shared__ __align__(16) float Ksm[CS][HD];
  __shared__ __align__(16) float Vsm[CS][HD];
  __shared__ __align__(16) float Qsm[CS][HD];
  __shared__ __align__(16) float P[HD][CS];
  __shared__ __align__(16) float PT[CS][HD+4];
  __shared__ __align__(16) float part[4][HD][CS];
  __shared__ __align__(16) float Xb[HD][CS];
  __shared__ float dots[CS][CS];
  __shared__ float Wc[CS][CS];
  __shared__ float cdec[CS];
  __shared__ float lam[HD], dg[HD];
  __shared__ float wred[4][CS];
  __shared__ float salpha[CS], sbeta[CS], sdonef[CS];

  // ---- load tiles + coefficients ----
  {
    const float4* Ks = (const float4*)(g_K + (size_t)g0*HD);
    const float4* Vs = (const float4*)(g_V + (size_t)g0*HD);
    const float4* Qs = (const float4*)(g_Q + (size_t)g0*HD);
    for (int idx = tid; idx < CS*HD/4; idx += 512){
      ((float4*)Ksm)[idx] = Ks[idx];
      ((float4*)Vsm)[idx] = Vs[idx];
      ((float4*)Qsm)[idx] = Qs[idx];
    }
  }
  if (tid < 64){
    int t_ = tid >> 3, s_ = tid & 7;
    float w = 0.f;
    if (s_ <= t_) w = g_beta[g0 + s_] * expf(g_G[g0 + t_] - g_G[g0 + s_]);
    Wc[t_][s_] = w;
  }
  if (tid < CS){
    float Gp = (c == 0) ? 0.f : g_G[g0 - 1];
    cdec[tid] = expf(g_G[g0 + tid] - Gp);
  }
  if (tid < HD){
    float z = lp[h*HD + i];
    float sp = (z > 20.f) ? z : log1pf(expf(z));
    lam[i] = sp + 0.25f;
  }
  float hkk[32], hkv[32];
  if (c == 0){
#pragma unroll
    for (int jj = 0; jj < 32; jj++){ hkk[jj] = 0.f; hkv[jj] = 0.f; }
  } else {
    size_t base = ((size_t)(bh*NC + (c-1)) << 14) + (size_t)i*HD + qq*32;
#pragma unroll
    for (int jj = 0; jj < 32; jj += 4){
      float4 a = *(const float4*)&g_Skk[base + jj];
      hkk[jj] = a.x; hkk[jj+1] = a.y; hkk[jj+2] = a.z; hkk[jj+3] = a.w;
      float4 v = *(const float4*)&g_Skv[base + jj];
      hkv[jj] = v.x; hkv[jj+1] = v.y; hkv[jj+2] = v.z; hkv[jj+3] = v.w;
    }
  }
  if (qq == (i >> 5)) dg[i] = hkk[i & 31];
  __syncthreads();

  // ---- x0 = b / (diagA + 1e-8) ----
  if (tid < HD){
#pragma unroll
    for (int t = 0; t < CS; t++){
      float diag = cdec[t]*dg[i] + lam[i];
#pragma unroll
      for (int s = 0; s < CS; s++){
        float kv = Ksm[s][i];
        diag += Wc[t][s] * kv * kv;
      }
      float xv = Qsm[t][i] / (diag + 1e-8f);
      Xb[i][t] = xv; P[i][t] = xv; PT[t][i] = xv;
    }
  }
  __syncthreads();

  // ---- r0 = b - A x0; p = r0; d0 ----
  float rv[CS], pv[CS];
  PHASE_A(hkk, Ksm);
  __syncthreads();
  if (tid < HD){
    float av[CS];
    ASSEMBLE(av);
#pragma unroll
    for (int t = 0; t < CS; t++){
      float r = Qsm[t][i] - (av[t] + lam[i]*Xb[i][t]);
      rv[t] = r; pv[t] = r;
    }
    float rr[CS];
#pragma unroll
    for (int t = 0; t < CS; t++) rr[t] = rv[t]*rv[t];
#pragma unroll
    for (int t = 0; t < CS; t++) rr[t] = warp_sum(rr[t]);
    if ((tid & 31) == 0){
#pragma unroll
      for (int t = 0; t < CS; t++) wred[i >> 5][t] = rr[t];
    }
#pragma unroll
    for (int t = 0; t < CS; t++){ P[i][t] = pv[t]; PT[t][i] = pv[t]; }
  }
  __syncthreads();
  float dmgr = 0.f; bool donem = false;
  if (tid < CS) dmgr = wred[0][tid] + wred[1][tid] + wred[2][tid] + wred[3][tid];

  // ---- CG iterations ----
  for (int it = 0; it < NCG; it++){
    PHASE_A(hkk, Ksm);
    __syncthreads();
    if (tid < HD){
      float qv[CS];
      ASSEMBLE(qv);
      float pq[CS];
#pragma unroll
      for (int t = 0; t < CS; t++){
        qv[t] += lam[i] * pv[t];
        pq[t] = pv[t] * qv[t];
      }
      // stash q in part[0][i][*] (this thread wrote it; free after ASSEMBLE)
      *(float4*)&part[0][i][0] = make_float4(qv[0], qv[1], qv[2], qv[3]);
      *(float4*)&part[0][i][4] = make_float4(qv[4], qv[5], qv[6], qv[7]);
#pragma unroll
      for (int t = 0; t < CS; t++) pq[t] = warp_sum(pq[t]);
      if ((tid & 31) == 0){
#pragma unroll
        for (int t = 0; t < CS; t++) wred[i >> 5][t] = pq[t];
      }
    }
    __syncthreads();
    if (tid < CS){
      float pq = wred[0][tid] + wred[1][tid] + wred[2][tid] + wred[3][tid];
      donem = donem || (dmgr < 1e-10f);
      donem = donem || (fabsf(pq) < 1e-10f);
      salpha[tid] = donem ? 0.f : dmgr / pq;
    }
    __syncthreads();
    if (tid < HD){
      float4 q0 = *(const float4*)&part[0][i][0];
      float4 q1 = *(const float4*)&part[0][i][4];
      float qv[CS] = {q0.x, q0.y, q0.z, q0.w, q1.x, q1.y, q1.z, q1.w};
      float rr[CS];
#pragma unroll
      for (int t = 0; t < CS; t++){
        float a = salpha[t];
        Xb[i][t] += a * pv[t];
        rv[t] -= a * qv[t];
        rr[t] = rv[t] * rv[t];
      }
#pragma unroll
      for (int t = 0; t < CS; t++) rr[t] = warp_sum(rr[t]);
      if ((tid & 31) == 0){
#pragma unroll
        for (int t = 0; t < CS; t++) wred[i >> 5][t] = rr[t];
      }
    }
    __syncthreads();
    if (tid < CS){
      float dn = wred[0][tid] + wred[1][tid] + wred[2][tid] + wred[3][tid];
      float bet = donem ? 0.f : dn / dmgr;
      if (!donem) dmgr = dn;
      sbeta[tid] = bet;
      sdonef[tid] = donem ? 1.f : 0.f;
    }
    __syncthreads();
    if (tid < HD){
#pragma unroll
      for (int t = 0; t < CS; t++){
        float pn = rv[t] + sbeta[t] * pv[t];
        pv[t] = (sdonef[t] != 0.f) ? pv[t] : pn;
        P[i][t] = pv[t]; PT[t][i] = pv[t];
      }
    }
    __syncthreads();
  }

  // ---- output: o_t = H_kv,t @ x_t ----
  if (tid < HD){
#pragma unroll
    for (int t = 0; t < CS; t++){
      float xv = Xb[i][t];
      P[i][t] = xv; PT[t][i] = xv;
    }
  }
  __syncthreads();
  PHASE_A(hkv, Vsm);
  __syncthreads();
  if (tid < HD){
    float ov[CS];
    ASSEMBLE(ov);
#pragma unroll
    for (int t = 0; t < CS; t++){
      int ts = c*CS + t;
      g_O[((size_t)(b*TT + ts)*NH + h)*HD + i] = ov[t];
    }
  }
}

// ------------------------- K8: rms norm -------------------------
__global__ void __launch_bounds__(128) k_rms(const float* __restrict__ w){
  int row = blockIdx.x;
  int i = threadIdx.x;
  float v = g_O[(size_t)row*HD + i];
  float ss = warp_sum(v*v);
  __shared__ float w4[4];
  if ((i & 31) == 0) w4[i >> 5] = ss;
  __syncthreads();
  float ms = (w4[0] + w4[1] + w4[2] + w4[3]) * (1.f/128.f);
  float rms = sqrtf(ms + 1e-6f);
  g_Of[(size_t)row*HD + i] = v / rms * w[i];
}

// ------------------------- K9: output projection (f32x2) ----------------------
__global__ void __launch_bounds__(256) k_out(const float* __restrict__ Wo,
                                             float* __restrict__ out){
  __shared__ __align__(16) float As[16][132];
  __shared__ __align__(16) float Bs[16][68];
  int tid = threadIdx.x;
  int ty = tid >> 4, tx = tid & 15;
  int m0 = blockIdx.y * 128, n0 = blockIdx.x * 64;
  ull acc2[4][4];
#pragma unroll
  for (int ii = 0; ii < 4; ii++)
#pragma unroll
    for (int jj = 0; jj < 4; jj++) acc2[ii][jj] = 0ull;

  for (int kb = 0; kb < HID; kb += 16){
#pragma unroll
    for (int it = 0; it < 2; it++){
      int f = tid*2 + it; int m = f >> 2, c4 = f & 3;
      float4 v = *(const float4*)&g_Of[(size_t)(m0 + m)*HID + kb + c4*4];
      As[c4*4+0][m] = v.x; As[c4*4+1][m] = v.y;
      As[c4*4+2][m] = v.z; As[c4*4+3][m] = v.w;
    }
    {
      int kk = tid >> 4, n4 = tid & 15;
      float4 v = *(const float4*)&Wo[(size_t)(kb + kk)*HID + n0 + n4*4];
      *(float4*)&Bs[kk][n4*4] = v;
    }
    __syncthreads();
#pragma unroll
    for (int k = 0; k < 16; k++){
      const ulonglong2* ap = (const ulonglong2*)&As[k][ty*8];
      ulonglong2 aA = ap[0], aB = ap[1];
      float4 bq = *(const float4*)&Bs[k][tx*4];
      ull b0 = bcast2(bq.x), b1 = bcast2(bq.y), b2 = bcast2(bq.z), b3 = bcast2(bq.w);
      ffma2(acc2[0][0], aA.x, b0); ffma2(acc2[0][1], aA.x, b1);
      ffma2(acc2[0][2], aA.x, b2); ffma2(acc2[0][3], aA.x, b3);
      ffma2(acc2[1][0], aA.y, b0); ffma2(acc2[1][1], aA.y, b1);
      ffma2(acc2[1][2], aA.y, b2); ffma2(acc2[1][3], aA.y, b3);
      ffma2(acc2[2][0], aB.x, b0); ffma2(acc2[2][1], aB.x, b1);
      ffma2(acc2[2][2], aB.x, b2); ffma2(acc2[2][3], aB.x, b3);
      ffma2(acc2[3][0], aB.y, b0); ffma2(acc2[3][1], aB.y, b1);
      ffma2(acc2[3][2], aB.y, b2); ffma2(acc2[3][3], aB.y, b3);
    }
    __syncthreads();
  }
#pragma unroll
  for (int m2 = 0; m2 < 4; m2++){
    float2 c0 = unpack2(acc2[m2][0]);
    float2 c1 = unpack2(acc2[m2][1]);
    float2 c2 = unpack2(acc2[m2][2]);
    float2 c3 = unpack2(acc2[m2][3]);
    int m = m0 + ty*8 + m2*2;
    *(float4*)&out[(size_t)m*HID + n0 + tx*4]     = make_float4(c0.x, c1.x, c2.x, c3.x);
    *(float4*)&out[(size_t)(m+1)*HID + n0 + tx*4] = make_float4(c0.y, c1.y, c2.y, c3.y);
  }
}

// ------------------------- launcher -------------------------
extern "C" void kernel_launch(void* const* d_in, const int* in_sizes, int n_in,
                              void* d_out, int out_size){
  const float* x    = (const float*)d_in[0];
  const float* Wq   = (const float*)d_in[1];
  const float* Wk   = (const float*)d_in[2];
  const float* Wv   = (const float*)d_in[3];
  const float* Wa   = (const float*)d_in[4];
  const float* ba   = (const float*)d_in[5];
  const float* Wb   = (const float*)d_in[6];
  const float* bb   = (const float*)d_in[7];
  const float* lpar = (const float*)d_in[8];
  const float* onw  = (const float*)d_in[9];
  const float* Wo   = (const float*)d_in[10];
  float* out = (float*)d_out;

  k_gates<<<MROWS, 256>>>(x, Wa, ba, Wb, bb);
  k_scanG<<<BH, 256>>>();
  k_qkv<<<dim3(32, 4, 3), 256>>>(x, Wq, Wk, Wv);
  k_l2<<<dim3(BH*TT, 2), 128>>>();
  k_chunksum<<<dim3(NC, BH), 256>>>();
  k_scan<<<dim3(BH, 64), 256>>>();
  k_solve<<<dim3(NC, BH), 512>>>(lpar);
  k_rms<<<MROWS*NH, 128>>>(onw);
  k_out<<<dim3(32, 4), 256>>>(Wo, out);
}